// round 5
// baseline (speedup 1.0000x reference)
#include <cuda_runtime.h>
#include <cuda_bf16.h>
#include <math.h>

// ---------------------------------------------------------------------------
// MLA prefill, fp32. B=2 S=2048 HID=2048 NH=16 NOPE=128 ROPE=64 VD=128
// QKD=192 KVR=512 QR=1536
// ---------------------------------------------------------------------------

#define Bv    2
#define Sv    2048
#define HIDv  2048
#define NHv   16
#define NOPEv 128
#define ROPEv 64
#define VDv   128
#define QKDv  192
#define KVRv  512
#define QRv   1536
#define Tv    (Bv * Sv)                 // 4096 tokens
#define KVDIM (KVRv + ROPEv)            // 576
#define QDIM  (NHv * QKDv)              // 3072
#define KVXD  (NHv * (NOPEv + VDv))     // 4096
#define ODIM  (NHv * VDv)               // 2048
#define SCALEv 0.07216878364870322f     // 192^-0.5

// ---- scratch (device globals: allocation-free) ----------------------------
__device__ float g_qlat[(size_t)Tv * QRv];
__device__ float g_q   [(size_t)Tv * QDIM];
__device__ float g_kv  [(size_t)Tv * KVDIM];
__device__ float g_kvx [(size_t)Tv * KVXD];
__device__ float g_kp  [(size_t)Tv * QDIM];
__device__ float g_attn[(size_t)Tv * ODIM];

// ---------------------------------------------------------------------------
// SGEMM: C[M,N] = A[M,K] * B[N,K]^T   (row-major, K contiguous; "NT")
// 128x128 tile, BK=16, 256 threads, 8x8 micro-tile, double-buffered smem
// with register prefetch: 1 __syncthreads per k-step, LDG latency hidden.
// Requires K%16==0, M%128==0; N edge guarded.
// ---------------------------------------------------------------------------
__global__ __launch_bounds__(256, 2)
void sgemm_nt(const float* __restrict__ A, int lda,
              const float* __restrict__ Bm, int ldb,
              float* __restrict__ C, int ldc,
              int M, int N, int K)
{
    __shared__ float As[2][16][132];
    __shared__ float Bs[2][16][132];

    const int tid = threadIdx.x;
    const int tx  = tid & 15;
    const int ty  = tid >> 4;
    const int m0  = blockIdx.y * 128;
    const int n0  = blockIdx.x * 128;

    // per-thread load coords (2 chunks of 256)
    int lrow[2], lc4[2];
#pragma unroll
    for (int l = 0; l < 2; l++) {
        int idx = tid + l * 256;
        lrow[l] = idx >> 2;
        lc4[l]  = (idx & 3) << 2;
    }

    float4 pa[2], pb[2];

    auto LOADG = [&](int k0) {
#pragma unroll
        for (int l = 0; l < 2; l++) {
            pa[l] = *(const float4*)(A + (size_t)(m0 + lrow[l]) * lda + k0 + lc4[l]);
            int n = n0 + lrow[l];
            pb[l] = make_float4(0.f, 0.f, 0.f, 0.f);
            if (n < N)
                pb[l] = *(const float4*)(Bm + (size_t)n * ldb + k0 + lc4[l]);
        }
    };
    auto STORES = [&](int buf) {
#pragma unroll
        for (int l = 0; l < 2; l++) {
            As[buf][lc4[l] + 0][lrow[l]] = pa[l].x;
            As[buf][lc4[l] + 1][lrow[l]] = pa[l].y;
            As[buf][lc4[l] + 2][lrow[l]] = pa[l].z;
            As[buf][lc4[l] + 3][lrow[l]] = pa[l].w;
            Bs[buf][lc4[l] + 0][lrow[l]] = pb[l].x;
            Bs[buf][lc4[l] + 1][lrow[l]] = pb[l].y;
            Bs[buf][lc4[l] + 2][lrow[l]] = pb[l].z;
            Bs[buf][lc4[l] + 3][lrow[l]] = pb[l].w;
        }
    };

    float acc[8][8];
#pragma unroll
    for (int i = 0; i < 8; i++)
#pragma unroll
        for (int j = 0; j < 8; j++) acc[i][j] = 0.f;

    LOADG(0);
    STORES(0);
    __syncthreads();

    int cur = 0;
    for (int k0 = 0; k0 < K; k0 += 16) {
        const bool has_next = (k0 + 16 < K);
        if (has_next) LOADG(k0 + 16);       // LDGs issue; consumed after compute

#pragma unroll
        for (int kk = 0; kk < 16; kk++) {
            float a[8], b[8];
            *(float4*)&a[0] = *(const float4*)&As[cur][kk][ty * 8];
            *(float4*)&a[4] = *(const float4*)&As[cur][kk][ty * 8 + 4];
            *(float4*)&b[0] = *(const float4*)&Bs[cur][kk][tx * 8];
            *(float4*)&b[4] = *(const float4*)&Bs[cur][kk][tx * 8 + 4];
#pragma unroll
            for (int i = 0; i < 8; i++)
#pragma unroll
                for (int j = 0; j < 8; j++)
                    acc[i][j] = fmaf(a[i], b[j], acc[i][j]);
        }

        if (has_next) STORES(cur ^ 1);
        __syncthreads();
        cur ^= 1;
    }

#pragma unroll
    for (int i = 0; i < 8; i++) {
        int m = m0 + ty * 8 + i;
        int n = n0 + tx * 8;
        if (m < M && n < N) {
            float* cp = C + (size_t)m * ldc + n;
            *(float4*)cp       = make_float4(acc[i][0], acc[i][1], acc[i][2], acc[i][3]);
            *(float4*)(cp + 4) = make_float4(acc[i][4], acc[i][5], acc[i][6], acc[i][7]);
        }
    }
}

// ---------------------------------------------------------------------------
// RMSNorm over rows x cols (row stride), in-place.
// ---------------------------------------------------------------------------
__global__ void rmsnorm_k(float* __restrict__ x, const float* __restrict__ gamma,
                          int cols, int stride)
{
    const int row = blockIdx.x;
    const int tid = threadIdx.x;
    float* p = x + (size_t)row * stride;

    float ss = 0.f;
    for (int i = tid; i < cols; i += 256) { float v = p[i]; ss += v * v; }
#pragma unroll
    for (int o = 16; o > 0; o >>= 1) ss += __shfl_xor_sync(0xffffffffu, ss, o);

    __shared__ float red[8];
    if ((tid & 31) == 0) red[tid >> 5] = ss;
    __syncthreads();
    if (tid < 8) {
        float v = red[tid];
#pragma unroll
        for (int o = 4; o > 0; o >>= 1) v += __shfl_xor_sync(0xffu, v, o);
        if (tid == 0) red[0] = v;
    }
    __syncthreads();

    const float inv = rsqrtf(red[0] / (float)cols + 1e-6f);
    for (int i = tid; i < cols; i += 256) p[i] = p[i] * inv * gamma[i];
}

// ---------------------------------------------------------------------------
// RoPE on q rope slice (per token, head, i<32), in-place.
// ---------------------------------------------------------------------------
__global__ void rope_q_k(float* __restrict__ q, const float* __restrict__ cosp,
                         const float* __restrict__ sinp)
{
    int idx = blockIdx.x * blockDim.x + threadIdx.x;
    if (idx >= Tv * NHv * 32) return;
    int t = idx >> 9;
    int r = idx & 511;
    int h = r >> 5;
    int i = r & 31;
    float* p = q + (size_t)t * QDIM + h * QKDv + NOPEv;
    float c0 = cosp[t * ROPEv + i],      s0 = sinp[t * ROPEv + i];
    float c1 = cosp[t * ROPEv + 32 + i], s1 = sinp[t * ROPEv + 32 + i];
    float x0 = p[i], x1 = p[i + 32];
    p[i]      = x0 * c0 - x1 * s0;
    p[i + 32] = x1 * c1 + x0 * s1;
}

// RoPE on shared k_rope (kv cols 512..575), in-place.
__global__ void rope_k_k(float* __restrict__ kv, const float* __restrict__ cosp,
                         const float* __restrict__ sinp)
{
    int idx = blockIdx.x * blockDim.x + threadIdx.x;
    if (idx >= Tv * 32) return;
    int t = idx >> 5;
    int i = idx & 31;
    float* p = kv + (size_t)t * KVDIM + KVRv;
    float c0 = cosp[t * ROPEv + i],      s0 = sinp[t * ROPEv + i];
    float c1 = cosp[t * ROPEv + 32 + i], s1 = sinp[t * ROPEv + 32 + i];
    float x0 = p[i], x1 = p[i + 32];
    p[i]      = x0 * c0 - x1 * s0;
    p[i + 32] = x1 * c1 + x0 * s1;
}

// Pack K per head: kp[t][h*192+d] = (d<128) ? kvx[t][h*256+d] : kv[t][512+d-128]
__global__ void kpack_k(const float* __restrict__ kvx, const float* __restrict__ kv,
                        float* __restrict__ kp)
{
    int idx = blockIdx.x * blockDim.x + threadIdx.x;
    if (idx >= Tv * QDIM) return;
    int t = idx / QDIM;
    int r = idx % QDIM;
    int h = r / QKDv;
    int d = r % QKDv;
    float v = (d < NOPEv) ? kvx[(size_t)t * KVXD + h * 256 + d]
                          : kv[(size_t)t * KVDIM + KVRv + (d - NOPEv)];
    kp[idx] = v;
}

// ---------------------------------------------------------------------------
// Causal flash attention, fp32. grid (S/32, NH, B), 256 threads.
// BQ=32 queries, BK=64 keys per tile. Static smem ~45 KB.
//  - K chunk stored transposed -> vectorized LDS.128 in S phase
//  - parallel online softmax (8 threads per query row)
// ---------------------------------------------------------------------------
#define BQ 32
#define BK 64
__global__ __launch_bounds__(256)
void attn_kernel(const float* __restrict__ Qg, const float* __restrict__ Kg,
                 const float* __restrict__ KVXg, float* __restrict__ Og)
{
    __shared__ float Qs[BQ][196];      // pre-scaled Q (broadcast reads)
    __shared__ float Ks[16][68];       // transposed K chunk: Ks[kk][key]
    __shared__ float Ss[BQ][65];       // scores -> probs
    __shared__ float Vs[16][128];      // V chunk
    __shared__ float s_m[BQ], s_l[BQ], s_alpha[BQ];

    const int tid = threadIdx.x;
    const int tx  = tid & 15;
    const int ty  = tid >> 4;
    const int q0  = blockIdx.x * BQ;
    const int h   = blockIdx.y;
    const int tb  = blockIdx.z * Sv;

    // load + scale Q tile
    for (int idx = tid; idx < BQ * 48; idx += 256) {
        int row = idx / 48;
        int c4  = (idx % 48) * 4;
        float4 v = *(const float4*)(Qg + (size_t)(tb + q0 + row) * QDIM + h * QKDv + c4);
        v.x *= SCALEv; v.y *= SCALEv; v.z *= SCALEv; v.w *= SCALEv;
        *(float4*)&Qs[row][c4] = v;
    }
    if (tid < BQ) { s_m[tid] = -1e30f; s_l[tid] = 0.f; }

    float acc[2][8];
#pragma unroll
    for (int i = 0; i < 2; i++)
#pragma unroll
        for (int j = 0; j < 8; j++) acc[i][j] = 0.f;

    const int ktmax = (q0 + BQ - 1) / BK;
    for (int kt = 0; kt <= ktmax; kt++) {
        const int k0 = kt * BK;

        // ---- S = Q K^T, chunked 16-wide over d=192 ----
        float sacc[2][4];
#pragma unroll
        for (int i = 0; i < 2; i++)
#pragma unroll
            for (int j = 0; j < 4; j++) sacc[i][j] = 0.f;

        for (int c = 0; c < 12; c++) {
            {
                int row = tid >> 2;          // key 0..63
                int c4  = (tid & 3) << 2;    // 0,4,8,12
                float4 v = *(const float4*)(Kg + (size_t)(tb + k0 + row) * QDIM
                                            + h * QKDv + c * 16 + c4);
                Ks[c4 + 0][row] = v.x; Ks[c4 + 1][row] = v.y;
                Ks[c4 + 2][row] = v.z; Ks[c4 + 3][row] = v.w;
            }
            __syncthreads();
#pragma unroll
            for (int kk = 0; kk < 16; kk++) {
                float a0 = Qs[ty * 2 + 0][c * 16 + kk];
                float a1 = Qs[ty * 2 + 1][c * 16 + kk];
                float bb[4];
                *(float4*)&bb[0] = *(const float4*)&Ks[kk][tx * 4];
#pragma unroll
                for (int j = 0; j < 4; j++) {
                    sacc[0][j] = fmaf(a0, bb[j], sacc[0][j]);
                    sacc[1][j] = fmaf(a1, bb[j], sacc[1][j]);
                }
            }
            __syncthreads();
        }

        // ---- causal mask + stage scores ----
#pragma unroll
        for (int i = 0; i < 2; i++) {
            int qg = q0 + ty * 2 + i;
#pragma unroll
            for (int j = 0; j < 4; j++) {
                int kg = k0 + tx * 4 + j;
                Ss[ty * 2 + i][tx * 4 + j] = (kg <= qg) ? sacc[i][j] : -1e30f;
            }
        }
        __syncthreads();

        // ---- parallel online softmax: 8 threads per query row ----
        {
            int r  = tid >> 3;          // 0..31
            int j0 = (tid & 7) * 8;     // 0,8,..,56
            float mold = s_m[r];
            float lm = -1e30f;
#pragma unroll
            for (int j = 0; j < 8; j++) lm = fmaxf(lm, Ss[r][j0 + j]);
#pragma unroll
            for (int o = 4; o > 0; o >>= 1)
                lm = fmaxf(lm, __shfl_xor_sync(0xffffffffu, lm, o));
            float mnew = fmaxf(mold, lm);
            float sum = 0.f;
#pragma unroll
            for (int j = 0; j < 8; j++) {
                float pv = __expf(Ss[r][j0 + j] - mnew);
                Ss[r][j0 + j] = pv;
                sum += pv;
            }
#pragma unroll
            for (int o = 4; o > 0; o >>= 1)
                sum += __shfl_xor_sync(0xffffffffu, sum, o);
            if ((tid & 7) == 0) {
                float alpha = __expf(mold - mnew);
                s_l[r]     = s_l[r] * alpha + sum;
                s_m[r]     = mnew;
                s_alpha[r] = alpha;
            }
        }
        __syncthreads();

        float al0 = s_alpha[ty * 2 + 0];
        float al1 = s_alpha[ty * 2 + 1];
#pragma unroll
        for (int j = 0; j < 8; j++) { acc[0][j] *= al0; acc[1][j] *= al1; }

        // ---- O += P V (V streamed 16 rows at a time from kvx) ----
        for (int kc = 0; kc < 4; kc++) {
            for (int idx = tid; idx < 512; idx += 256) {
                int row = idx >> 5;
                int c4  = (idx & 31) << 2;
                float4 v = *(const float4*)(KVXg + (size_t)(tb + k0 + kc * 16 + row) * KVXD
                                            + h * 256 + NOPEv + c4);
                *(float4*)&Vs[row][c4] = v;
            }
            __syncthreads();
#pragma unroll
            for (int kk = 0; kk < 16; kk++) {
                float p0 = Ss[ty * 2 + 0][kc * 16 + kk];
                float p1 = Ss[ty * 2 + 1][kc * 16 + kk];
                float vv[8];
                *(float4*)&vv[0] = *(const float4*)&Vs[kk][tx * 8];
                *(float4*)&vv[4] = *(const float4*)&Vs[kk][tx * 8 + 4];
#pragma unroll
                for (int j = 0; j < 8; j++) {
                    acc[0][j] = fmaf(p0, vv[j], acc[0][j]);
                    acc[1][j] = fmaf(p1, vv[j], acc[1][j]);
                }
            }
            __syncthreads();
        }
    }

    // ---- normalize + store ----
#pragma unroll
    for (int i = 0; i < 2; i++) {
        int r = ty * 2 + i;
        float inv = 1.0f / s_l[r];
        float* op = Og + (size_t)(tb + q0 + r) * ODIM + h * VDv + tx * 8;
        *(float4*)op       = make_float4(acc[i][0] * inv, acc[i][1] * inv,
                                         acc[i][2] * inv, acc[i][3] * inv);
        *(float4*)(op + 4) = make_float4(acc[i][4] * inv, acc[i][5] * inv,
                                         acc[i][6] * inv, acc[i][7] * inv);
    }
}

// ---------------------------------------------------------------------------
extern "C" void kernel_launch(void* const* d_in, const int* in_sizes, int n_in,
                              void* d_out, int out_size)
{
    const float* hid      = (const float*)d_in[0];
    const float* cosp     = (const float*)d_in[1];
    const float* sinp     = (const float*)d_in[2];
    const float* Wq_down  = (const float*)d_in[3];
    const float* q_gamma  = (const float*)d_in[4];
    const float* Wq_up    = (const float*)d_in[5];
    const float* Wkv_down = (const float*)d_in[6];
    const float* kv_gamma = (const float*)d_in[7];
    const float* Wkv_up   = (const float*)d_in[8];
    const float* Wo       = (const float*)d_in[9];
    float* out = (float*)d_out;

    float *qlat, *q, *kv, *kvx, *kp, *attn;
    cudaGetSymbolAddress((void**)&qlat, g_qlat);
    cudaGetSymbolAddress((void**)&q,    g_q);
    cudaGetSymbolAddress((void**)&kv,   g_kv);
    cudaGetSymbolAddress((void**)&kvx,  g_kvx);
    cudaGetSymbolAddress((void**)&kp,   g_kp);
    cudaGetSymbolAddress((void**)&attn, g_attn);

    const dim3 blk(256);

    // 1) q latent: [T,1536] = hid @ Wq_down^T
    sgemm_nt<<<dim3(QRv / 128, Tv / 128), blk>>>(hid, HIDv, Wq_down, HIDv,
                                                 qlat, QRv, Tv, QRv, HIDv);
    // 2) rmsnorm(q_lat)
    rmsnorm_k<<<Tv, 256>>>(qlat, q_gamma, QRv, QRv);
    // 3) q: [T,3072] = q_lat @ Wq_up^T
    sgemm_nt<<<dim3(QDIM / 128, Tv / 128), blk>>>(qlat, QRv, Wq_up, QRv,
                                                  q, QDIM, Tv, QDIM, QRv);
    // 4) rope on q
    rope_q_k<<<(Tv * NHv * 32) / 256, 256>>>(q, cosp, sinp);
    // 5) kv: [T,576] = hid @ Wkv_down^T
    sgemm_nt<<<dim3((KVDIM + 127) / 128, Tv / 128), blk>>>(hid, HIDv, Wkv_down, HIDv,
                                                           kv, KVDIM, Tv, KVDIM, HIDv);
    // 6) rmsnorm(c_kv) on first 512 cols
    rmsnorm_k<<<Tv, 256>>>(kv, kv_gamma, KVRv, KVDIM);
    // 7) rope on shared k_rope (cols 512..575)
    rope_k_k<<<(Tv * 32) / 256, 256>>>(kv, cosp, sinp);
    // 8) kvx: [T,4096] = c_kv_norm @ Wkv_up^T
    sgemm_nt<<<dim3(KVXD / 128, Tv / 128), blk>>>(kv, KVDIM, Wkv_up, KVRv,
                                                  kvx, KVXD, Tv, KVXD, KVRv);
    // 9) pack per-head K = [k_nope | k_rope]
    kpack_k<<<(Tv * QDIM) / 256, 256>>>(kvx, kv, kp);
    // 10) causal attention
    attn_kernel<<<dim3(Sv / BQ, NHv, Bv), 256>>>(q, kp, kvx, attn);
    // 11) output projection
    sgemm_nt<<<dim3(HIDv / 128, Tv / 128), blk>>>(attn, ODIM, Wo, ODIM,
                                                  out, HIDv, Tv, HIDv, ODIM);
}

// round 6
// speedup vs baseline: 1.0062x; 1.0062x over previous
#include <cuda_runtime.h>
#include <cuda_bf16.h>
#include <math.h>

// ---------------------------------------------------------------------------
// MLA prefill, fp32. B=2 S=2048 HID=2048 NH=16 NOPE=128 ROPE=64 VD=128
// QKD=192 KVR=512 QR=1536
// ---------------------------------------------------------------------------

#define Bv    2
#define Sv    2048
#define HIDv  2048
#define NHv   16
#define NOPEv 128
#define ROPEv 64
#define VDv   128
#define QKDv  192
#define KVRv  512
#define QRv   1536
#define Tv    (Bv * Sv)                 // 4096 tokens
#define KVDIM (KVRv + ROPEv)            // 576
#define QDIM  (NHv * QKDv)              // 3072
#define KVXD  (NHv * (NOPEv + VDv))     // 4096
#define ODIM  (NHv * VDv)               // 2048
#define SCALEv 0.07216878364870322f     // 192^-0.5

// ---- scratch (device globals: allocation-free) ----------------------------
__device__ float g_qlat[(size_t)Tv * QRv];
__device__ float g_q   [(size_t)Tv * QDIM];
__device__ float g_kv  [(size_t)Tv * KVDIM];
__device__ float g_kvx [(size_t)Tv * KVXD];
__device__ float g_kp  [(size_t)Tv * QDIM];
__device__ float g_attn[(size_t)Tv * ODIM];

// ---------------------------------------------------------------------------
// SGEMM: C[M,N] = A[M,K] * B[N,K]^T   (row-major, K contiguous; "NT")
// 128x128 tile, BK=16, 256 threads, 8x8 micro-tile, double-buffered smem
// with register prefetch: 1 __syncthreads per k-step, LDG latency hidden.
// Requires K%16==0, M%128==0; N edge guarded.
// ---------------------------------------------------------------------------
__global__ __launch_bounds__(256, 2)
void sgemm_nt(const float* __restrict__ A, int lda,
              const float* __restrict__ Bm, int ldb,
              float* __restrict__ C, int ldc,
              int M, int N, int K)
{
    __shared__ float As[2][16][132];
    __shared__ float Bs[2][16][132];

    const int tid = threadIdx.x;
    const int tx  = tid & 15;
    const int ty  = tid >> 4;
    const int m0  = blockIdx.y * 128;
    const int n0  = blockIdx.x * 128;

    // per-thread load coords (2 chunks of 256)
    int lrow[2], lc4[2];
#pragma unroll
    for (int l = 0; l < 2; l++) {
        int idx = tid + l * 256;
        lrow[l] = idx >> 2;
        lc4[l]  = (idx & 3) << 2;
    }

    float4 pa[2], pb[2];

    auto LOADG = [&](int k0) {
#pragma unroll
        for (int l = 0; l < 2; l++) {
            pa[l] = *(const float4*)(A + (size_t)(m0 + lrow[l]) * lda + k0 + lc4[l]);
            int n = n0 + lrow[l];
            pb[l] = make_float4(0.f, 0.f, 0.f, 0.f);
            if (n < N)
                pb[l] = *(const float4*)(Bm + (size_t)n * ldb + k0 + lc4[l]);
        }
    };
    auto STORES = [&](int buf) {
#pragma unroll
        for (int l = 0; l < 2; l++) {
            As[buf][lc4[l] + 0][lrow[l]] = pa[l].x;
            As[buf][lc4[l] + 1][lrow[l]] = pa[l].y;
            As[buf][lc4[l] + 2][lrow[l]] = pa[l].z;
            As[buf][lc4[l] + 3][lrow[l]] = pa[l].w;
            Bs[buf][lc4[l] + 0][lrow[l]] = pb[l].x;
            Bs[buf][lc4[l] + 1][lrow[l]] = pb[l].y;
            Bs[buf][lc4[l] + 2][lrow[l]] = pb[l].z;
            Bs[buf][lc4[l] + 3][lrow[l]] = pb[l].w;
        }
    };

    float acc[8][8];
#pragma unroll
    for (int i = 0; i < 8; i++)
#pragma unroll
        for (int j = 0; j < 8; j++) acc[i][j] = 0.f;

    LOADG(0);
    STORES(0);
    __syncthreads();

    int cur = 0;
    for (int k0 = 0; k0 < K; k0 += 16) {
        const bool has_next = (k0 + 16 < K);
        if (has_next) LOADG(k0 + 16);       // LDGs issue; consumed after compute

#pragma unroll
        for (int kk = 0; kk < 16; kk++) {
            float a[8], b[8];
            *(float4*)&a[0] = *(const float4*)&As[cur][kk][ty * 8];
            *(float4*)&a[4] = *(const float4*)&As[cur][kk][ty * 8 + 4];
            *(float4*)&b[0] = *(const float4*)&Bs[cur][kk][tx * 8];
            *(float4*)&b[4] = *(const float4*)&Bs[cur][kk][tx * 8 + 4];
#pragma unroll
            for (int i = 0; i < 8; i++)
#pragma unroll
                for (int j = 0; j < 8; j++)
                    acc[i][j] = fmaf(a[i], b[j], acc[i][j]);
        }

        if (has_next) STORES(cur ^ 1);
        __syncthreads();
        cur ^= 1;
    }

#pragma unroll
    for (int i = 0; i < 8; i++) {
        int m = m0 + ty * 8 + i;
        int n = n0 + tx * 8;
        if (m < M && n < N) {
            float* cp = C + (size_t)m * ldc + n;
            *(float4*)cp       = make_float4(acc[i][0], acc[i][1], acc[i][2], acc[i][3]);
            *(float4*)(cp + 4) = make_float4(acc[i][4], acc[i][5], acc[i][6], acc[i][7]);
        }
    }
}

// ---------------------------------------------------------------------------
// RMSNorm over rows x cols (row stride), in-place.
// ---------------------------------------------------------------------------
__global__ void rmsnorm_k(float* __restrict__ x, const float* __restrict__ gamma,
                          int cols, int stride)
{
    const int row = blockIdx.x;
    const int tid = threadIdx.x;
    float* p = x + (size_t)row * stride;

    float ss = 0.f;
    for (int i = tid; i < cols; i += 256) { float v = p[i]; ss += v * v; }
#pragma unroll
    for (int o = 16; o > 0; o >>= 1) ss += __shfl_xor_sync(0xffffffffu, ss, o);

    __shared__ float red[8];
    if ((tid & 31) == 0) red[tid >> 5] = ss;
    __syncthreads();
    if (tid < 8) {
        float v = red[tid];
#pragma unroll
        for (int o = 4; o > 0; o >>= 1) v += __shfl_xor_sync(0xffu, v, o);
        if (tid == 0) red[0] = v;
    }
    __syncthreads();

    const float inv = rsqrtf(red[0] / (float)cols + 1e-6f);
    for (int i = tid; i < cols; i += 256) p[i] = p[i] * inv * gamma[i];
}

// ---------------------------------------------------------------------------
// RoPE on q rope slice (per token, head, i<32), in-place.
// ---------------------------------------------------------------------------
__global__ void rope_q_k(float* __restrict__ q, const float* __restrict__ cosp,
                         const float* __restrict__ sinp)
{
    int idx = blockIdx.x * blockDim.x + threadIdx.x;
    if (idx >= Tv * NHv * 32) return;
    int t = idx >> 9;
    int r = idx & 511;
    int h = r >> 5;
    int i = r & 31;
    float* p = q + (size_t)t * QDIM + h * QKDv + NOPEv;
    float c0 = cosp[t * ROPEv + i],      s0 = sinp[t * ROPEv + i];
    float c1 = cosp[t * ROPEv + 32 + i], s1 = sinp[t * ROPEv + 32 + i];
    float x0 = p[i], x1 = p[i + 32];
    p[i]      = x0 * c0 - x1 * s0;
    p[i + 32] = x1 * c1 + x0 * s1;
}

// RoPE on shared k_rope (kv cols 512..575), in-place.
__global__ void rope_k_k(float* __restrict__ kv, const float* __restrict__ cosp,
                         const float* __restrict__ sinp)
{
    int idx = blockIdx.x * blockDim.x + threadIdx.x;
    if (idx >= Tv * 32) return;
    int t = idx >> 5;
    int i = idx & 31;
    float* p = kv + (size_t)t * KVDIM + KVRv;
    float c0 = cosp[t * ROPEv + i],      s0 = sinp[t * ROPEv + i];
    float c1 = cosp[t * ROPEv + 32 + i], s1 = sinp[t * ROPEv + 32 + i];
    float x0 = p[i], x1 = p[i + 32];
    p[i]      = x0 * c0 - x1 * s0;
    p[i + 32] = x1 * c1 + x0 * s1;
}

// Pack K per head: kp[t][h*192+d] = (d<128) ? kvx[t][h*256+d] : kv[t][512+d-128]
__global__ void kpack_k(const float* __restrict__ kvx, const float* __restrict__ kv,
                        float* __restrict__ kp)
{
    int idx = blockIdx.x * blockDim.x + threadIdx.x;
    if (idx >= Tv * QDIM) return;
    int t = idx / QDIM;
    int r = idx % QDIM;
    int h = r / QKDv;
    int d = r % QKDv;
    float v = (d < NOPEv) ? kvx[(size_t)t * KVXD + h * 256 + d]
                          : kv[(size_t)t * KVDIM + KVRv + (d - NOPEv)];
    kp[idx] = v;
}

// ---------------------------------------------------------------------------
// Causal flash attention, fp32. grid (S/32, NH, B), 256 threads.
// BQ=32 queries, BK=64 keys per tile. Static smem ~45 KB.
//  - K chunk stored transposed -> vectorized LDS.128 in S phase
//  - parallel online softmax (8 threads per query row)
// ---------------------------------------------------------------------------
#define BQ 32
#define BK 64
__global__ __launch_bounds__(256)
void attn_kernel(const float* __restrict__ Qg, const float* __restrict__ Kg,
                 const float* __restrict__ KVXg, float* __restrict__ Og)
{
    __shared__ float Qs[BQ][196];      // pre-scaled Q (broadcast reads)
    __shared__ float Ks[16][68];       // transposed K chunk: Ks[kk][key]
    __shared__ float Ss[BQ][65];       // scores -> probs
    __shared__ float Vs[16][128];      // V chunk
    __shared__ float s_m[BQ], s_l[BQ], s_alpha[BQ];

    const int tid = threadIdx.x;
    const int tx  = tid & 15;
    const int ty  = tid >> 4;
    const int q0  = blockIdx.x * BQ;
    const int h   = blockIdx.y;
    const int tb  = blockIdx.z * Sv;

    // load + scale Q tile
    for (int idx = tid; idx < BQ * 48; idx += 256) {
        int row = idx / 48;
        int c4  = (idx % 48) * 4;
        float4 v = *(const float4*)(Qg + (size_t)(tb + q0 + row) * QDIM + h * QKDv + c4);
        v.x *= SCALEv; v.y *= SCALEv; v.z *= SCALEv; v.w *= SCALEv;
        *(float4*)&Qs[row][c4] = v;
    }
    if (tid < BQ) { s_m[tid] = -1e30f; s_l[tid] = 0.f; }

    float acc[2][8];
#pragma unroll
    for (int i = 0; i < 2; i++)
#pragma unroll
        for (int j = 0; j < 8; j++) acc[i][j] = 0.f;

    const int ktmax = (q0 + BQ - 1) / BK;
    for (int kt = 0; kt <= ktmax; kt++) {
        const int k0 = kt * BK;

        // ---- S = Q K^T, chunked 16-wide over d=192 ----
        float sacc[2][4];
#pragma unroll
        for (int i = 0; i < 2; i++)
#pragma unroll
            for (int j = 0; j < 4; j++) sacc[i][j] = 0.f;

        for (int c = 0; c < 12; c++) {
            {
                int row = tid >> 2;          // key 0..63
                int c4  = (tid & 3) << 2;    // 0,4,8,12
                float4 v = *(const float4*)(Kg + (size_t)(tb + k0 + row) * QDIM
                                            + h * QKDv + c * 16 + c4);
                Ks[c4 + 0][row] = v.x; Ks[c4 + 1][row] = v.y;
                Ks[c4 + 2][row] = v.z; Ks[c4 + 3][row] = v.w;
            }
            __syncthreads();
#pragma unroll
            for (int kk = 0; kk < 16; kk++) {
                float a0 = Qs[ty * 2 + 0][c * 16 + kk];
                float a1 = Qs[ty * 2 + 1][c * 16 + kk];
                float bb[4];
                *(float4*)&bb[0] = *(const float4*)&Ks[kk][tx * 4];
#pragma unroll
                for (int j = 0; j < 4; j++) {
                    sacc[0][j] = fmaf(a0, bb[j], sacc[0][j]);
                    sacc[1][j] = fmaf(a1, bb[j], sacc[1][j]);
                }
            }
            __syncthreads();
        }

        // ---- causal mask + stage scores ----
#pragma unroll
        for (int i = 0; i < 2; i++) {
            int qg = q0 + ty * 2 + i;
#pragma unroll
            for (int j = 0; j < 4; j++) {
                int kg = k0 + tx * 4 + j;
                Ss[ty * 2 + i][tx * 4 + j] = (kg <= qg) ? sacc[i][j] : -1e30f;
            }
        }
        __syncthreads();

        // ---- parallel online softmax: 8 threads per query row ----
        {
            int r  = tid >> 3;          // 0..31
            int j0 = (tid & 7) * 8;     // 0,8,..,56
            float mold = s_m[r];
            float lm = -1e30f;
#pragma unroll
            for (int j = 0; j < 8; j++) lm = fmaxf(lm, Ss[r][j0 + j]);
#pragma unroll
            for (int o = 4; o > 0; o >>= 1)
                lm = fmaxf(lm, __shfl_xor_sync(0xffffffffu, lm, o));
            float mnew = fmaxf(mold, lm);
            float sum = 0.f;
#pragma unroll
            for (int j = 0; j < 8; j++) {
                float pv = __expf(Ss[r][j0 + j] - mnew);
                Ss[r][j0 + j] = pv;
                sum += pv;
            }
#pragma unroll
            for (int o = 4; o > 0; o >>= 1)
                sum += __shfl_xor_sync(0xffffffffu, sum, o);
            if ((tid & 7) == 0) {
                float alpha = __expf(mold - mnew);
                s_l[r]     = s_l[r] * alpha + sum;
                s_m[r]     = mnew;
                s_alpha[r] = alpha;
            }
        }
        __syncthreads();

        float al0 = s_alpha[ty * 2 + 0];
        float al1 = s_alpha[ty * 2 + 1];
#pragma unroll
        for (int j = 0; j < 8; j++) { acc[0][j] *= al0; acc[1][j] *= al1; }

        // ---- O += P V (V streamed 16 rows at a time from kvx) ----
        for (int kc = 0; kc < 4; kc++) {
            for (int idx = tid; idx < 512; idx += 256) {
                int row = idx >> 5;
                int c4  = (idx & 31) << 2;
                float4 v = *(const float4*)(KVXg + (size_t)(tb + k0 + kc * 16 + row) * KVXD
                                            + h * 256 + NOPEv + c4);
                *(float4*)&Vs[row][c4] = v;
            }
            __syncthreads();
#pragma unroll
            for (int kk = 0; kk < 16; kk++) {
                float p0 = Ss[ty * 2 + 0][kc * 16 + kk];
                float p1 = Ss[ty * 2 + 1][kc * 16 + kk];
                float vv[8];
                *(float4*)&vv[0] = *(const float4*)&Vs[kk][tx * 8];
                *(float4*)&vv[4] = *(const float4*)&Vs[kk][tx * 8 + 4];
#pragma unroll
                for (int j = 0; j < 8; j++) {
                    acc[0][j] = fmaf(p0, vv[j], acc[0][j]);
                    acc[1][j] = fmaf(p1, vv[j], acc[1][j]);
                }
            }
            __syncthreads();
        }
    }

    // ---- normalize + store ----
#pragma unroll
    for (int i = 0; i < 2; i++) {
        int r = ty * 2 + i;
        float inv = 1.0f / s_l[r];
        float* op = Og + (size_t)(tb + q0 + r) * ODIM + h * VDv + tx * 8;
        *(float4*)op       = make_float4(acc[i][0] * inv, acc[i][1] * inv,
                                         acc[i][2] * inv, acc[i][3] * inv);
        *(float4*)(op + 4) = make_float4(acc[i][4] * inv, acc[i][5] * inv,
                                         acc[i][6] * inv, acc[i][7] * inv);
    }
}

// ---------------------------------------------------------------------------
extern "C" void kernel_launch(void* const* d_in, const int* in_sizes, int n_in,
                              void* d_out, int out_size)
{
    const float* hid      = (const float*)d_in[0];
    const float* cosp     = (const float*)d_in[1];
    const float* sinp     = (const float*)d_in[2];
    const float* Wq_down  = (const float*)d_in[3];
    const float* q_gamma  = (const float*)d_in[4];
    const float* Wq_up    = (const float*)d_in[5];
    const float* Wkv_down = (const float*)d_in[6];
    const float* kv_gamma = (const float*)d_in[7];
    const float* Wkv_up   = (const float*)d_in[8];
    const float* Wo       = (const float*)d_in[9];
    float* out = (float*)d_out;

    float *qlat, *q, *kv, *kvx, *kp, *attn;
    cudaGetSymbolAddress((void**)&qlat, g_qlat);
    cudaGetSymbolAddress((void**)&q,    g_q);
    cudaGetSymbolAddress((void**)&kv,   g_kv);
    cudaGetSymbolAddress((void**)&kvx,  g_kvx);
    cudaGetSymbolAddress((void**)&kp,   g_kp);
    cudaGetSymbolAddress((void**)&attn, g_attn);

    const dim3 blk(256);

    // 1) q latent: [T,1536] = hid @ Wq_down^T
    sgemm_nt<<<dim3(QRv / 128, Tv / 128), blk>>>(hid, HIDv, Wq_down, HIDv,
                                                 qlat, QRv, Tv, QRv, HIDv);
    // 2) rmsnorm(q_lat)
    rmsnorm_k<<<Tv, 256>>>(qlat, q_gamma, QRv, QRv);
    // 3) q: [T,3072] = q_lat @ Wq_up^T
    sgemm_nt<<<dim3(QDIM / 128, Tv / 128), blk>>>(qlat, QRv, Wq_up, QRv,
                                                  q, QDIM, Tv, QDIM, QRv);
    // 4) rope on q
    rope_q_k<<<(Tv * NHv * 32) / 256, 256>>>(q, cosp, sinp);
    // 5) kv: [T,576] = hid @ Wkv_down^T
    sgemm_nt<<<dim3((KVDIM + 127) / 128, Tv / 128), blk>>>(hid, HIDv, Wkv_down, HIDv,
                                                           kv, KVDIM, Tv, KVDIM, HIDv);
    // 6) rmsnorm(c_kv) on first 512 cols
    rmsnorm_k<<<Tv, 256>>>(kv, kv_gamma, KVRv, KVDIM);
    // 7) rope on shared k_rope (cols 512..575)
    rope_k_k<<<(Tv * 32) / 256, 256>>>(kv, cosp, sinp);
    // 8) kvx: [T,4096] = c_kv_norm @ Wkv_up^T
    sgemm_nt<<<dim3(KVXD / 128, Tv / 128), blk>>>(kv, KVDIM, Wkv_up, KVRv,
                                                  kvx, KVXD, Tv, KVXD, KVRv);
    // 9) pack per-head K = [k_nope | k_rope]
    kpack_k<<<(Tv * QDIM) / 256, 256>>>(kvx, kv, kp);
    // 10) causal attention
    attn_kernel<<<dim3(Sv / BQ, NHv, Bv), 256>>>(q, kp, kvx, attn);
    // 11) output projection
    sgemm_nt<<<dim3(HIDv / 128, Tv / 128), blk>>>(attn, ODIM, Wo, ODIM,
                                                  out, HIDv, Tv, HIDv, ODIM);
}